// round 1
// baseline (speedup 1.0000x reference)
#include <cuda_runtime.h>
#include <math.h>

// ---------------------------------------------------------------------------
// Problem constants
// ---------------------------------------------------------------------------
#define N_NODES 4681
#define BDIM    64
#define MEMD    256
#define NS      (BDIM*MEMD)      // 16384 floats per node
#define LEAF_START 585
#define N_LEAVES   4096

// ---------------------------------------------------------------------------
// Scratch (static device globals -- no runtime allocation allowed)
// ---------------------------------------------------------------------------
__device__ float g_c[(size_t)N_NODES*NS];      // 307 MB
__device__ float g_h[(size_t)N_NODES*NS];      // 307 MB
__device__ float g_hf[(size_t)4096*NS];        // 268 MB  child h @ Wfh^T (no bias)
__device__ float g_fx[(size_t)512*NS];         // 33.5 MB parent x @ Wfx^T + bfx
__device__ float g_hsum[(size_t)512*NS];       // 33.5 MB
__device__ float g_iou[(size_t)512*BDIM*768];  // 100 MB

typedef unsigned long long u64;

// ---------------------------------------------------------------------------
// f32x2 packed-FMA helpers (Blackwell; ptxas never emits FFMA2 from C++)
// ---------------------------------------------------------------------------
__device__ __forceinline__ u64 bcast2(float a) {
    u64 r; asm("mov.b64 %0, {%1, %1};" : "=l"(r) : "f"(a)); return r;
}
__device__ __forceinline__ void ffma2(u64 &d, u64 a, u64 b) {
    asm("fma.rn.f32x2 %0, %1, %2, %3;" : "=l"(d) : "l"(a), "l"(b), "l"(d));
}
__device__ __forceinline__ float2 unp(u64 v) {
    float2 r; asm("mov.b64 {%0, %1}, %2;" : "=f"(r.x), "=f"(r.y) : "l"(v)); return r;
}
union F4U { float4 f; u64 u[2]; };

__device__ __forceinline__ float sigf(float x) { return 1.0f / (1.0f + expf(-x)); }

// ---------------------------------------------------------------------------
// Generic SGEMM:  C[M, Nout] = A1 @ W1^T (+ A2 @ W2^T) (+ b1) (+ b2)
//   A: [M, 256] row-major.  W: [Nout, 256] row-major.  K fixed = 256 per phase.
//   Tile: BM=128, BN=64, BK=32; 256 threads; each thread 8 rows x 4 cols.
//   f32x2: row-pairs come free from LDS.128 of transposed A; columns broadcast.
// ---------------------------------------------------------------------------
#define ASTR 132   // padded stride: conflict-light STS, 16B-aligned LDS.128
#define BSTR 68

struct TileRegs { float4 a[4]; float4 b[2]; };

__device__ __forceinline__ void load_tile(TileRegs &R,
    const float* __restrict__ A, const float* __restrict__ W,
    int k0, int rowBase, int n0, int M, int t)
{
#pragma unroll
    for (int i = 0; i < 4; i++) {
        int idx = t + i * 256;
        int r = idx >> 3, kq = idx & 7;
        int gr = rowBase + r;
        if (gr < M) R.a[i] = *(const float4*)(A + (size_t)gr * 256 + k0 + kq * 4);
        else        R.a[i] = make_float4(0.f, 0.f, 0.f, 0.f);
    }
#pragma unroll
    for (int i = 0; i < 2; i++) {
        int idx = t + i * 256;
        int n = idx >> 3, kq = idx & 7;
        R.b[i] = *(const float4*)(W + (size_t)(n0 + n) * 256 + k0 + kq * 4);
    }
}

__global__ __launch_bounds__(256, 2) void sgemm_k256(
    const float* __restrict__ A1, const float* __restrict__ A2,
    const float* __restrict__ W1, const float* __restrict__ W2,
    const float* __restrict__ b1, const float* __restrict__ b2,
    float* __restrict__ C, int M, int ldc)
{
    __shared__ float As[32][ASTR];
    __shared__ float Bs[32][BSTR];
    const int t = threadIdx.x;
    const int tx = t & 15, ty = t >> 4;
    const int rowBase = blockIdx.x * 128;
    const int n0 = blockIdx.y * 64;

    u64 acc[4][4];   // [row-pair][col]
#pragma unroll
    for (int i = 0; i < 4; i++)
#pragma unroll
        for (int j = 0; j < 4; j++) acc[i][j] = 0ULL;

    const int nTiles = (A2 != nullptr) ? 16 : 8;

    TileRegs R;
    load_tile(R, A1, W1, 0, rowBase, n0, M, t);

    for (int kt = 0; kt < nTiles; kt++) {
        // stage registers -> smem (A transposed)
#pragma unroll
        for (int i = 0; i < 4; i++) {
            int idx = t + i * 256;
            int r = idx >> 3, kq = idx & 7;
            As[kq * 4 + 0][r] = R.a[i].x;
            As[kq * 4 + 1][r] = R.a[i].y;
            As[kq * 4 + 2][r] = R.a[i].z;
            As[kq * 4 + 3][r] = R.a[i].w;
        }
#pragma unroll
        for (int i = 0; i < 2; i++) {
            int idx = t + i * 256;
            int n = idx >> 3, kq = idx & 7;
            Bs[kq * 4 + 0][n] = R.b[i].x;
            Bs[kq * 4 + 1][n] = R.b[i].y;
            Bs[kq * 4 + 2][n] = R.b[i].z;
            Bs[kq * 4 + 3][n] = R.b[i].w;
        }
        __syncthreads();

        if (kt + 1 < nTiles) {  // prefetch next tile into registers
            int kn = kt + 1;
            const float* A = (kn < 8) ? A1 : A2;
            const float* W = (kn < 8) ? W1 : W2;
            load_tile(R, A, W, (kn & 7) * 32, rowBase, n0, M, t);
        }

#pragma unroll
        for (int kk = 0; kk < 32; kk++) {
            F4U a0, a1, b4;
            a0.f = *(const float4*)&As[kk][ty * 4];
            a1.f = *(const float4*)&As[kk][64 + ty * 4];
            b4.f = *(const float4*)&Bs[kk][tx * 4];
            u64 bb0 = bcast2(b4.f.x), bb1 = bcast2(b4.f.y);
            u64 bb2 = bcast2(b4.f.z), bb3 = bcast2(b4.f.w);
            ffma2(acc[0][0], a0.u[0], bb0); ffma2(acc[0][1], a0.u[0], bb1);
            ffma2(acc[0][2], a0.u[0], bb2); ffma2(acc[0][3], a0.u[0], bb3);
            ffma2(acc[1][0], a0.u[1], bb0); ffma2(acc[1][1], a0.u[1], bb1);
            ffma2(acc[1][2], a0.u[1], bb2); ffma2(acc[1][3], a0.u[1], bb3);
            ffma2(acc[2][0], a1.u[0], bb0); ffma2(acc[2][1], a1.u[0], bb1);
            ffma2(acc[2][2], a1.u[0], bb2); ffma2(acc[2][3], a1.u[0], bb3);
            ffma2(acc[3][0], a1.u[1], bb0); ffma2(acc[3][1], a1.u[1], bb1);
            ffma2(acc[3][2], a1.u[1], bb2); ffma2(acc[3][3], a1.u[1], bb3);
        }
        __syncthreads();
    }

    // epilogue
    float bias[4] = {0.f, 0.f, 0.f, 0.f};
    if (b1) {
#pragma unroll
        for (int c = 0; c < 4; c++) bias[c] += b1[n0 + tx * 4 + c];
    }
    if (b2) {
#pragma unroll
        for (int c = 0; c < 4; c++) bias[c] += b2[n0 + tx * 4 + c];
    }
#pragma unroll
    for (int rp = 0; rp < 4; rp++) {
        int localr = (rp < 2) ? (ty * 4 + rp * 2) : (64 + ty * 4 + (rp - 2) * 2);
        float2 v0 = unp(acc[rp][0]), v1 = unp(acc[rp][1]);
        float2 v2 = unp(acc[rp][2]), v3 = unp(acc[rp][3]);
#pragma unroll
        for (int e = 0; e < 2; e++) {
            int gr = rowBase + localr + e;
            if (gr < M) {
                float4 o;
                o.x = (e ? v0.y : v0.x) + bias[0];
                o.y = (e ? v1.y : v1.x) + bias[1];
                o.z = (e ? v2.y : v2.x) + bias[2];
                o.w = (e ? v3.y : v3.x) + bias[3];
                *(float4*)(C + (size_t)gr * ldc + n0 + tx * 4) = o;
            }
        }
    }
}

// ---------------------------------------------------------------------------
// Leaf kernel: fused iou GEMM + activation for the 4096 leaf nodes.
//   M = 262144 rows (node-major, contiguous), K = 256.
//   Structured N: each CTA computes a 64-wide m-slice for groups i/o/u
//   (W rows m, 256+m, 512+m) so the activation fuses in registers.
// ---------------------------------------------------------------------------
__global__ __launch_bounds__(256, 2) void leaf_kernel(
    const float* __restrict__ X,
    const float* __restrict__ Wioux,
    const float* __restrict__ bioux, const float* __restrict__ biouh)
{
    __shared__ float As[32][BSTR];
    __shared__ float Bs[3][32][BSTR];
    const int t = threadIdx.x;
    const int tx = t & 15, ty = t >> 4;
    const int rowBase = blockIdx.x * 64;
    const int m0 = blockIdx.y * 64;

    u64 acc[3][4][2];  // [group][row][col-pair]
#pragma unroll
    for (int g = 0; g < 3; g++)
#pragma unroll
        for (int r = 0; r < 4; r++) { acc[g][r][0] = 0ULL; acc[g][r][1] = 0ULL; }

    float4 ra[2], rb[3][2];
    // prefetch k0 = 0
#pragma unroll
    for (int i = 0; i < 2; i++) {
        int idx = t + i * 256; int r = idx >> 3, kq = idx & 7;
        ra[i] = *(const float4*)(X + (size_t)(rowBase + r) * 256 + kq * 4);
    }
#pragma unroll
    for (int g = 0; g < 3; g++)
#pragma unroll
        for (int i = 0; i < 2; i++) {
            int idx = t + i * 256; int n = idx >> 3, kq = idx & 7;
            rb[g][i] = *(const float4*)(Wioux + (size_t)(g * 256 + m0 + n) * 256 + kq * 4);
        }

    for (int kt = 0; kt < 8; kt++) {
#pragma unroll
        for (int i = 0; i < 2; i++) {
            int idx = t + i * 256; int r = idx >> 3, kq = idx & 7;
            As[kq * 4 + 0][r] = ra[i].x; As[kq * 4 + 1][r] = ra[i].y;
            As[kq * 4 + 2][r] = ra[i].z; As[kq * 4 + 3][r] = ra[i].w;
        }
#pragma unroll
        for (int g = 0; g < 3; g++)
#pragma unroll
            for (int i = 0; i < 2; i++) {
                int idx = t + i * 256; int n = idx >> 3, kq = idx & 7;
                Bs[g][kq * 4 + 0][n] = rb[g][i].x; Bs[g][kq * 4 + 1][n] = rb[g][i].y;
                Bs[g][kq * 4 + 2][n] = rb[g][i].z; Bs[g][kq * 4 + 3][n] = rb[g][i].w;
            }
        __syncthreads();

        if (kt + 1 < 8) {
            int k0 = (kt + 1) * 32;
#pragma unroll
            for (int i = 0; i < 2; i++) {
                int idx = t + i * 256; int r = idx >> 3, kq = idx & 7;
                ra[i] = *(const float4*)(X + (size_t)(rowBase + r) * 256 + k0 + kq * 4);
            }
#pragma unroll
            for (int g = 0; g < 3; g++)
#pragma unroll
                for (int i = 0; i < 2; i++) {
                    int idx = t + i * 256; int n = idx >> 3, kq = idx & 7;
                    rb[g][i] = *(const float4*)(Wioux + (size_t)(g * 256 + m0 + n) * 256 + k0 + kq * 4);
                }
        }

#pragma unroll
        for (int kk = 0; kk < 32; kk++) {
            F4U a; a.f = *(const float4*)&As[kk][ty * 4];
            u64 ab0 = bcast2(a.f.x), ab1 = bcast2(a.f.y);
            u64 ab2 = bcast2(a.f.z), ab3 = bcast2(a.f.w);
#pragma unroll
            for (int g = 0; g < 3; g++) {
                F4U b; b.f = *(const float4*)&Bs[g][kk][tx * 4];
                ffma2(acc[g][0][0], ab0, b.u[0]); ffma2(acc[g][0][1], ab0, b.u[1]);
                ffma2(acc[g][1][0], ab1, b.u[0]); ffma2(acc[g][1][1], ab1, b.u[1]);
                ffma2(acc[g][2][0], ab2, b.u[0]); ffma2(acc[g][2][1], ab2, b.u[1]);
                ffma2(acc[g][3][0], ab3, b.u[0]); ffma2(acc[g][3][1], ab3, b.u[1]);
            }
        }
        __syncthreads();
    }

    // epilogue: activation, write c/h
    const int m = m0 + tx * 4;
    float bi[4], bo[4], bu[4];
#pragma unroll
    for (int c = 0; c < 4; c++) {
        bi[c] = bioux[m + c]       + biouh[m + c];
        bo[c] = bioux[256 + m + c] + biouh[256 + m + c];
        bu[c] = bioux[512 + m + c] + biouh[512 + m + c];
    }
#pragma unroll
    for (int r = 0; r < 4; r++) {
        int gr = rowBase + ty * 4 + r;
        size_t off = (size_t)(LEAF_START * BDIM + gr) * 256 + m;
        float2 i01 = unp(acc[0][r][0]), i23 = unp(acc[0][r][1]);
        float2 o01 = unp(acc[1][r][0]), o23 = unp(acc[1][r][1]);
        float2 u01 = unp(acc[2][r][0]), u23 = unp(acc[2][r][1]);
        float iv[4] = {i01.x, i01.y, i23.x, i23.y};
        float ov[4] = {o01.x, o01.y, o23.x, o23.y};
        float uv[4] = {u01.x, u01.y, u23.x, u23.y};
        float4 cv, hv;
        float cc, hh;
#pragma unroll
        for (int c = 0; c < 4; c++) {
            cc = sigf(iv[c] + bi[c]) * tanhf(uv[c] + bu[c]);
            hh = sigf(ov[c] + bo[c]) * tanhf(cc);
            (&cv.x)[c] = cc; (&hv.x)[c] = hh;
        }
        *(float4*)(g_c + off) = cv;
        *(float4*)(g_h + off) = hv;
    }
}

// ---------------------------------------------------------------------------
// hsum: hsum[p] = sum_j prob[p, child_j] * h[child_j]
// ---------------------------------------------------------------------------
__global__ void hsum_kernel(const float* __restrict__ prob, int s, int cnt)
{
    int idx = blockIdx.x * blockDim.x + threadIdx.x;
    if (idx >= cnt * NS) return;
    int p = idx >> 14;
    int r = idx & (NS - 1);
    int pg = s + p;
    int cg = 8 * pg + 1;
    const float* pr = prob + (size_t)pg * N_NODES + cg;
    float acc = 0.f;
#pragma unroll
    for (int j = 0; j < 8; j++)
        acc += pr[j] * g_h[(size_t)(cg + j) * NS + r];
    g_hsum[idx] = acc;
}

// ---------------------------------------------------------------------------
// final: forget gates + cell/hidden activation for parents of one level
// ---------------------------------------------------------------------------
__global__ void final_kernel(const float* __restrict__ prob,
                             const float* __restrict__ bfh, int s, int cnt)
{
    int idx = blockIdx.x * blockDim.x + threadIdx.x;
    if (idx >= cnt * NS) return;
    int p = idx >> 14;
    int r = idx & (NS - 1);
    int m = idx & 255;
    int row = idx >> 8;               // p*64 + b
    int pg = s + p;
    int cg = 8 * pg + 1;

    const float* iou = g_iou + (size_t)row * 768 + m;
    float iv = iou[0], ov = iou[256], uv = iou[512];
    float fxv = g_fx[idx];
    float bf = bfh[m];

    const float* pr = prob + (size_t)pg * N_NODES + cg;
    float acc = 0.f;
#pragma unroll
    for (int j = 0; j < 8; j++) {
        float pw  = pr[j];
        float hf  = g_hf[(size_t)(8 * p + j) * NS + r];
        float cch = g_c[(size_t)(cg + j) * NS + r];
        float f = sigf(pw * hf + bf + fxv);
        acc += f * pw * cch;
    }
    float cc = sigf(iv) * tanhf(uv) + acc;
    float hh = sigf(ov) * tanhf(cc);
    g_c[(size_t)pg * NS + r] = cc;
    g_h[(size_t)pg * NS + r] = hh;
}

__global__ void copy_out_kernel(float* __restrict__ out)
{
    int i = blockIdx.x * blockDim.x + threadIdx.x;
    if (i < NS)          out[i] = g_c[i];
    else if (i < 2 * NS) out[i] = g_h[i - NS];
}

// ---------------------------------------------------------------------------
// kernel_launch: leaf level, then levels d = 3..0, then copy out.
// ---------------------------------------------------------------------------
extern "C" void kernel_launch(void* const* d_in, const int* in_sizes, int n_in,
                              void* d_out, int out_size)
{
    const float* inputs = (const float*)d_in[0];
    const float* prob   = (const float*)d_in[1];
    const float* Wioux  = (const float*)d_in[2];
    const float* bioux  = (const float*)d_in[3];
    const float* Wiouh  = (const float*)d_in[4];
    const float* biouh  = (const float*)d_in[5];
    const float* Wfx    = (const float*)d_in[6];
    const float* bfx    = (const float*)d_in[7];
    const float* Wfh    = (const float*)d_in[8];
    const float* bfh    = (const float*)d_in[9];
    float* out = (float*)d_out;

    float *pc, *ph, *phf, *pfx, *phsum, *piou;
    cudaGetSymbolAddress((void**)&pc,    g_c);
    cudaGetSymbolAddress((void**)&ph,    g_h);
    cudaGetSymbolAddress((void**)&phf,   g_hf);
    cudaGetSymbolAddress((void**)&pfx,   g_fx);
    cudaGetSymbolAddress((void**)&phsum, g_hsum);
    cudaGetSymbolAddress((void**)&piou,  g_iou);

    // Leaf level: 262144 x 256 -> fused c/h for nodes 585..4680
    leaf_kernel<<<dim3(N_LEAVES, 4), 256>>>(
        inputs + (size_t)LEAF_START * NS, Wioux, bioux, biouh);

    const int starts[5] = {0, 1, 9, 73, 585};
    const int counts[5] = {1, 8, 64, 512, 4096};

    for (int d = 3; d >= 0; d--) {
        int s = starts[d], cnt = counts[d], cs = starts[d + 1];
        int nch = cnt * 8;
        int Mh = nch * BDIM;     // child rows
        int Mp = cnt * BDIM;     // parent rows

        // hf_raw = h[children] @ Wfh^T   (no bias)
        sgemm_k256<<<dim3((Mh + 127) / 128, 4), 256>>>(
            ph + (size_t)cs * NS, nullptr, Wfh, nullptr,
            nullptr, nullptr, phf, Mh, 256);

        // fx = x[parents] @ Wfx^T + bfx
        sgemm_k256<<<dim3((Mp + 127) / 128, 4), 256>>>(
            inputs + (size_t)s * NS, nullptr, Wfx, nullptr,
            bfx, nullptr, pfx, Mp, 256);

        // hsum[p] = sum_j pw_j * h_child_j
        hsum_kernel<<<(cnt * NS + 255) / 256, 256>>>(prob, s, cnt);

        // iou = x @ Wioux^T + hsum @ Wiouh^T + bioux + biouh
        sgemm_k256<<<dim3((Mp + 127) / 128, 12), 256>>>(
            inputs + (size_t)s * NS, phsum, Wioux, Wiouh,
            bioux, biouh, piou, Mp, 768);

        // gates + activation -> c/h for parents
        final_kernel<<<(cnt * NS + 255) / 256, 256>>>(prob, bfh, s, cnt);
    }

    copy_out_kernel<<<(2 * NS + 255) / 256, 256>>>(out);
}

// round 3
// speedup vs baseline: 1.8547x; 1.8547x over previous
#include <cuda_runtime.h>
#include <cuda_bf16.h>
#include <math.h>
#include <stdint.h>

#define N_NODES 4681
#define BDIM    64
#define NS      16384
#define LEAF_START 585

typedef unsigned short u16;
typedef unsigned int   u32;
typedef unsigned long long u64;

// ---------------------------------------------------------------------------
// Static device scratch
// ---------------------------------------------------------------------------
__device__ __align__(256) float g_c  [(size_t)N_NODES*NS];
__device__ __align__(256) u16   g_hhi[(size_t)N_NODES*NS];
__device__ __align__(256) u16   g_hlo[(size_t)N_NODES*NS];
__device__ __align__(256) u16   g_xhi[(size_t)N_NODES*NS];
__device__ __align__(256) u16   g_xlo[(size_t)N_NODES*NS];
__device__ __align__(256) float g_hf [(size_t)4096*NS];
__device__ __align__(256) float g_fx [(size_t)512*NS];
__device__ __align__(256) u16   g_shi[(size_t)512*NS];
__device__ __align__(256) u16   g_slo[(size_t)512*NS];
__device__ __align__(256) float g_iou[(size_t)512*BDIM*768];
__device__ __align__(256) u16 g_Wxh[768*256],  g_Wxl[768*256];
__device__ __align__(256) u16 g_Whh[768*256],  g_Whl[768*256];
__device__ __align__(256) u16 g_Wfxh[256*256], g_Wfxl[256*256];
__device__ __align__(256) u16 g_Wfhh[256*256], g_Wfhl[256*256];

// ---------------------------------------------------------------------------
// Helpers
// ---------------------------------------------------------------------------
__device__ __forceinline__ float sig_fast(float x){ return 1.f/(1.f+__expf(-x)); }
__device__ __forceinline__ float tanh_fast(float x){ return 1.f - 2.f/(__expf(2.f*x)+1.f); }
__device__ __forceinline__ u16 f2bf(float x){ __nv_bfloat16 b = __float2bfloat16(x); return *(u16*)&b; }
__device__ __forceinline__ float bf2f(u16 v){ __nv_bfloat16 b = *(__nv_bfloat16*)&v; return __bfloat162float(b); }

__device__ __forceinline__ u32 smem_u32(const void* p){
    u32 a; asm("{ .reg .u64 t; cvta.to.shared.u64 t, %1; cvt.u32.u64 %0, t; }" : "=r"(a) : "l"(p)); return a;
}
__device__ __forceinline__ void cp16(u32 d, const void* s){
    asm volatile("cp.async.cg.shared.global [%0], [%1], 16;" :: "r"(d), "l"(s));
}
__device__ __forceinline__ void cp_commit(){ asm volatile("cp.async.commit_group;" ::: "memory"); }
__device__ __forceinline__ void cp_wait0(){ asm volatile("cp.async.wait_group 0;" ::: "memory"); }
__device__ __forceinline__ void cp_wait1(){ asm volatile("cp.async.wait_group 1;" ::: "memory"); }

__device__ __forceinline__ void ldsm4(u32 &r0,u32 &r1,u32 &r2,u32 &r3, u32 addr){
    asm volatile("ldmatrix.sync.aligned.m8n8.x4.shared.b16 {%0,%1,%2,%3}, [%4];"
        : "=r"(r0),"=r"(r1),"=r"(r2),"=r"(r3) : "r"(addr));
}
__device__ __forceinline__ void mma16816(float* c, const u32* a, const u32* b){
    asm volatile("mma.sync.aligned.m16n8k16.row.col.f32.bf16.bf16.f32 "
        "{%0,%1,%2,%3}, {%4,%5,%6,%7}, {%8,%9}, {%0,%1,%2,%3};"
        : "+f"(c[0]),"+f"(c[1]),"+f"(c[2]),"+f"(c[3])
        : "r"(a[0]),"r"(a[1]),"r"(a[2]),"r"(a[3]), "r"(b[0]),"r"(b[1]));
}

#define SWZ(o) ((u32)(o) ^ (((u32)(o)>>3)&0x70u))

// smem layout:
//   A bufs: [0, 16K), [16K, 32K)
//   plain B bufs: [32K, 40K), [40K, 48K);  bias at 49152 (64 floats)
//   leaf  B bufs: [32K, 56K), [56K, 80K);  bias at 81920 (192 floats)
#define SMEM_PLAIN (49152 + 256)
#define SMEM_LEAF  (81920 + 768)

// ---------------------------------------------------------------------------
// fp32 -> bf16 hi/lo split
// ---------------------------------------------------------------------------
__global__ void split_kernel(const float* __restrict__ src,
                             u16* __restrict__ hi, u16* __restrict__ lo, size_t n4)
{
    size_t i = (size_t)blockIdx.x*blockDim.x + threadIdx.x;
    if (i >= n4) return;
    float4 v = ((const float4*)src)[i];
    u16 h[4], l[4];
#pragma unroll
    for (int j=0;j<4;j++){
        float x = (&v.x)[j];
        u16 hb = f2bf(x);
        h[j] = hb; l[j] = f2bf(x - bf2f(hb));
    }
    ((ushort4*)hi)[i] = make_ushort4(h[0],h[1],h[2],h[3]);
    ((ushort4*)lo)[i] = make_ushort4(l[0],l[1],l[2],l[3]);
}

// ---------------------------------------------------------------------------
// Chunk loaders (cp.async, swizzled)
// ---------------------------------------------------------------------------
__device__ __forceinline__ void load_A_chunk(u32 aB, const u16* __restrict__ Ah,
    int rowBase, int kc, int M, int t)
{
#pragma unroll
    for (int i=0;i<4;i++){
        int e = t + i*256; int r = e>>3, s = e&7;
        int gr = rowBase + r; if (gr >= M) gr = M-1;
        cp16(aB + SWZ(r*128 + s*16), Ah + (size_t)gr*256 + kc + s*8);
    }
}
__device__ __forceinline__ void load_B_chunk64(u32 bB, const u16* __restrict__ Wh,
    int n0, int kc, int t)
{
#pragma unroll
    for (int i=0;i<2;i++){
        int e = t + i*256; int n = e>>3, s = e&7;
        cp16(bB + SWZ(n*128 + s*16), Wh + (size_t)(n0+n)*256 + kc + s*8);
    }
}

// ---------------------------------------------------------------------------
// gemm_plain: C[M, Nout] = A1@W1^T (+ A2@W2^T) (+ b1) (+ b2)
//   A, W bf16 hi/lo, 3-pass split per source. ldc = Nout.
// ---------------------------------------------------------------------------
__global__ void __launch_bounds__(256) gemm_plain(
    const u16* __restrict__ A1h, const u16* __restrict__ A1l,
    const u16* __restrict__ A2h, const u16* __restrict__ A2l,
    const u16* __restrict__ W1h, const u16* __restrict__ W1l,
    const u16* __restrict__ W2h, const u16* __restrict__ W2l,
    const float* __restrict__ b1, const float* __restrict__ b2,
    float* __restrict__ Cout, int M, int ldc)
{
    extern __shared__ __align__(1024) char smem[];
    const u32 sb = smem_u32(smem);
    const int t = threadIdx.x;
    const int n0 = blockIdx.x*64;
    const int rowBase = blockIdx.y*128;
    float* biasS = (float*)(smem + 49152);

    for (int i=t;i<64;i+=256){
        float v = 0.f;
        if (b1) v += b1[n0+i];
        if (b2) v += b2[n0+i];
        biasS[i] = v;
    }

    float C[2][4][4];
#pragma unroll
    for (int a=0;a<2;a++)
#pragma unroll
    for (int b=0;b<4;b++)
#pragma unroll
    for (int cc=0;cc<4;cc++) C[a][b][cc]=0.f;

    const int nc = (A2h != nullptr) ? 24 : 12;

    // chunk c: src=c/12, q=c%12, pass=q/4 (0:hh 1:hl 2:lh), kc=(q&3)*64
#define SEL_A(c) ((((c)%12)/4)==2 ? (((c)/12)? A2l:A1l) : (((c)/12)? A2h:A1h))
#define SEL_W(c) ((((c)%12)/4)==1 ? (((c)/12)? W2l:W1l) : (((c)/12)? W2h:W1h))
#define KC(c)    ((((c)%12)&3)*64)

    load_A_chunk(sb, SEL_A(0), rowBase, KC(0), M, t);
    load_B_chunk64(sb + 32768u, SEL_W(0), n0, KC(0), t);
    cp_commit();

    const int lane=t&31, wid=t>>5;
    const int wm=(wid&3)*32, wn=(wid>>2)*32;
    const u32 aRow  = (u32)(wm + (lane&15));
    const u32 aCol0 = (u32)((lane>>4)*16);
    const u32 bRow  = (u32)(wn + (lane&7) + ((lane>>4)&1)*8);
    const u32 bCol0 = (u32)(((lane>>3)&1)*16);

    for (int c=0;c<nc;c++){
        if (c+1<nc){
            int nb=(c+1)&1;
            load_A_chunk(sb + nb*16384u, SEL_A(c+1), rowBase, KC(c+1), M, t);
            load_B_chunk64(sb + 32768u + nb*8192u, SEL_W(c+1), n0, KC(c+1), t);
            cp_commit();
            cp_wait1();
        } else cp_wait0();
        __syncthreads();

        const u32 aB = sb + (u32)(c&1)*16384u;
        const u32 bB = sb + 32768u + (u32)(c&1)*8192u;
#pragma unroll
        for (int ks=0;ks<4;ks++){
            u32 a0[4], a1[4], b0[4], b1f[4];
            ldsm4(a0[0],a0[1],a0[2],a0[3], aB + SWZ(aRow*128      + ks*32 + aCol0));
            ldsm4(a1[0],a1[1],a1[2],a1[3], aB + SWZ((aRow+16)*128 + ks*32 + aCol0));
            ldsm4(b0[0],b0[1],b0[2],b0[3], bB + SWZ(bRow*128      + ks*32 + bCol0));
            ldsm4(b1f[0],b1f[1],b1f[2],b1f[3], bB + SWZ((bRow+16)*128 + ks*32 + bCol0));
            mma16816(C[0][0], a0, b0+0); mma16816(C[0][1], a0, b0+2);
            mma16816(C[0][2], a0, b1f+0); mma16816(C[0][3], a0, b1f+2);
            mma16816(C[1][0], a1, b0+0); mma16816(C[1][1], a1, b0+2);
            mma16816(C[1][2], a1, b1f+0); mma16816(C[1][3], a1, b1f+2);
        }
        if (c+1<nc) __syncthreads();
    }
#undef SEL_A
#undef SEL_W
#undef KC

    // epilogue
#pragma unroll
    for (int mt=0;mt<2;mt++){
        int r0 = rowBase + wm + mt*16 + (lane>>2);
#pragma unroll
        for (int nt=0;nt<4;nt++){
            int cl = wn + nt*8 + (lane&3)*2;
            float bz0 = biasS[cl], bz1 = biasS[cl+1];
            if (r0 < M)
                *(float2*)(Cout + (size_t)r0*ldc + n0 + cl) =
                    make_float2(C[mt][nt][0]+bz0, C[mt][nt][1]+bz1);
            if (r0+8 < M)
                *(float2*)(Cout + (size_t)(r0+8)*ldc + n0 + cl) =
                    make_float2(C[mt][nt][2]+bz0, C[mt][nt][3]+bz1);
        }
    }
}

// ---------------------------------------------------------------------------
// gemm_leaf: fused iou GEMM + LSTM activation for leaves.
//   Block computes cols {m0..m0+64} of groups i/o/u (W rows g*256+m0+n).
//   Writes g_c (fp32), g_hhi/g_hlo (bf16 split). M divisible by 128.
// ---------------------------------------------------------------------------
__global__ void __launch_bounds__(256) gemm_leaf(
    const u16* __restrict__ Ah_, const u16* __restrict__ Al_,
    const u16* __restrict__ Wh_, const u16* __restrict__ Wl_,
    const float* __restrict__ bx, const float* __restrict__ bh,
    int M, int outRowBase)
{
    extern __shared__ __align__(1024) char smem[];
    const u32 sb = smem_u32(smem);
    const int t = threadIdx.x;
    const int m0 = blockIdx.x*64;
    const int rowBase = blockIdx.y*128;
    float* biasS = (float*)(smem + 81920);

    for (int i=t;i<192;i+=256){
        int g=i>>6, cc=i&63;
        biasS[i] = bx[g*256+m0+cc] + bh[g*256+m0+cc];
    }

    float Cg[3][2][4][4];
#pragma unroll
    for (int g=0;g<3;g++)
#pragma unroll
    for (int a=0;a<2;a++)
#pragma unroll
    for (int b=0;b<4;b++)
#pragma unroll
    for (int cc=0;cc<4;cc++) Cg[g][a][b][cc]=0.f;

#define LSEL_A(c) (((c)/4)==2 ? Al_ : Ah_)
#define LSEL_W(c) (((c)/4)==1 ? Wl_ : Wh_)
#define LKC(c)    (((c)&3)*64)

    // B load: 3 groups x 64 rows x 8 segs = 1536 ops
#define LOAD_LEAF_B(bB, Wp, kc) \
    { _Pragma("unroll") \
      for (int i=0;i<6;i++){ \
        int e = t + i*256; int g = e>>9, f = e&511, n = f>>3, s = f&7; \
        cp16((bB) + (u32)g*8192u + SWZ(n*128 + s*16), \
             (Wp) + (size_t)(g*256 + m0 + n)*256 + (kc) + s*8); } }

    load_A_chunk(sb, LSEL_A(0), rowBase, LKC(0), M, t);
    LOAD_LEAF_B(sb + 32768u, LSEL_W(0), LKC(0));
    cp_commit();

    const int lane=t&31, wid=t>>5;
    const int wm=(wid&3)*32, wn=(wid>>2)*32;
    const u32 aRow  = (u32)(wm + (lane&15));
    const u32 aCol0 = (u32)((lane>>4)*16);
    const u32 bRow  = (u32)(wn + (lane&7) + ((lane>>4)&1)*8);
    const u32 bCol0 = (u32)(((lane>>3)&1)*16);

    for (int c=0;c<12;c++){
        if (c+1<12){
            int nb=(c+1)&1;
            load_A_chunk(sb + nb*16384u, LSEL_A(c+1), rowBase, LKC(c+1), M, t);
            LOAD_LEAF_B(sb + 32768u + (u32)nb*24576u, LSEL_W(c+1), LKC(c+1));
            cp_commit();
            cp_wait1();
        } else cp_wait0();
        __syncthreads();

        const u32 aB = sb + (u32)(c&1)*16384u;
        const u32 bB = sb + 32768u + (u32)(c&1)*24576u;
#pragma unroll
        for (int ks=0;ks<4;ks++){
            u32 a0[4], a1[4];
            ldsm4(a0[0],a0[1],a0[2],a0[3], aB + SWZ(aRow*128      + ks*32 + aCol0));
            ldsm4(a1[0],a1[1],a1[2],a1[3], aB + SWZ((aRow+16)*128 + ks*32 + aCol0));
#pragma unroll
            for (int g=0;g<3;g++){
                u32 b0[4], b1f[4];
                u32 gB = bB + (u32)g*8192u;
                ldsm4(b0[0],b0[1],b0[2],b0[3],   gB + SWZ(bRow*128      + ks*32 + bCol0));
                ldsm4(b1f[0],b1f[1],b1f[2],b1f[3], gB + SWZ((bRow+16)*128 + ks*32 + bCol0));
                mma16816(Cg[g][0][0], a0, b0+0); mma16816(Cg[g][0][1], a0, b0+2);
                mma16816(Cg[g][0][2], a0, b1f+0); mma16816(Cg[g][0][3], a0, b1f+2);
                mma16816(Cg[g][1][0], a1, b0+0); mma16816(Cg[g][1][1], a1, b0+2);
                mma16816(Cg[g][1][2], a1, b1f+0); mma16816(Cg[g][1][3], a1, b1f+2);
            }
        }
        if (c+1<12) __syncthreads();
    }
#undef LSEL_A
#undef LSEL_W
#undef LKC
#undef LOAD_LEAF_B

    // fused LSTM epilogue
#pragma unroll
    for (int mt=0;mt<2;mt++){
        int rb = wm + mt*16 + (lane>>2);
#pragma unroll
        for (int h2=0;h2<2;h2++){
            int row = rowBase + rb + h2*8;
#pragma unroll
            for (int nt=0;nt<4;nt++){
                int cl = wn + nt*8 + (lane&3)*2;
                float cs2[2]; u16 hh2[2], hl2[2];
#pragma unroll
                for (int e=0;e<2;e++){
                    float iv = Cg[0][mt][nt][h2*2+e] + biasS[cl+e];
                    float ov = Cg[1][mt][nt][h2*2+e] + biasS[64+cl+e];
                    float uv = Cg[2][mt][nt][h2*2+e] + biasS[128+cl+e];
                    float c_ = sig_fast(iv)*tanh_fast(uv);
                    float h_ = sig_fast(ov)*tanh_fast(c_);
                    cs2[e]=c_;
                    u16 hb=f2bf(h_); hh2[e]=hb; hl2[e]=f2bf(h_-bf2f(hb));
                }
                size_t idx = ((size_t)(outRowBase+row))*256 + m0 + cl;
                *(float2*)(g_c+idx) = make_float2(cs2[0],cs2[1]);
                *(u32*)(g_hhi+idx)  = (u32)hh2[0] | ((u32)hh2[1]<<16);
                *(u32*)(g_hlo+idx)  = (u32)hl2[0] | ((u32)hl2[1]<<16);
            }
        }
    }
}

// ---------------------------------------------------------------------------
// hsum[p] = sum_j prob[p,child_j] * h[child_j]; output bf16 hi/lo
// ---------------------------------------------------------------------------
__global__ void hsum_kernel(const float* __restrict__ prob, int s, int cnt)
{
    int idx = blockIdx.x*blockDim.x + threadIdx.x;
    if (idx >= cnt*NS) return;
    int p = idx >> 14, r = idx & (NS-1);
    int pg = s + p, cg = 8*pg + 1;
    const float* pr = prob + (size_t)pg*N_NODES + cg;
    float acc = 0.f;
#pragma unroll
    for (int j=0;j<8;j++){
        size_t o = (size_t)(cg+j)*NS + r;
        acc += pr[j] * (bf2f(g_hhi[o]) + bf2f(g_hlo[o]));
    }
    u16 hb = f2bf(acc);
    g_shi[idx] = hb;
    g_slo[idx] = f2bf(acc - bf2f(hb));
}

// ---------------------------------------------------------------------------
// final: forget gates + cell/hidden activation
// ---------------------------------------------------------------------------
__global__ void final_kernel(const float* __restrict__ prob,
                             const float* __restrict__ bfh, int s, int cnt)
{
    int idx = blockIdx.x*blockDim.x + threadIdx.x;
    if (idx >= cnt*NS) return;
    int p = idx >> 14, r = idx & (NS-1);
    int m = idx & 255;
    int row = idx >> 8;
    int pg = s + p, cg = 8*pg + 1;

    const float* iou = g_iou + (size_t)row*768 + m;
    float iv = iou[0], ov = iou[256], uv = iou[512];
    float fxv = g_fx[idx];
    float bf = bfh[m];

    const float* pr = prob + (size_t)pg*N_NODES + cg;
    float acc = 0.f;
#pragma unroll
    for (int j=0;j<8;j++){
        float pw  = pr[j];
        float hf  = g_hf[(size_t)(8*p+j)*NS + r];
        float cch = g_c[(size_t)(cg+j)*NS + r];
        float f = sig_fast(pw*hf + bf + fxv);
        acc += f * pw * cch;
    }
    float cc = sig_fast(iv)*tanh_fast(uv) + acc;
    float hh = sig_fast(ov)*tanh_fast(cc);
    g_c[(size_t)pg*NS + r] = cc;
    u16 hb = f2bf(hh);
    g_hhi[(size_t)pg*NS + r] = hb;
    g_hlo[(size_t)pg*NS + r] = f2bf(hh - bf2f(hb));
}

__global__ void copy_out_kernel(float* __restrict__ out)
{
    int i = blockIdx.x*blockDim.x + threadIdx.x;
    if (i < NS)          out[i] = g_c[i];
    else if (i < 2*NS)   out[i] = bf2f(g_hhi[i-NS]) + bf2f(g_hlo[i-NS]);
}

// ---------------------------------------------------------------------------
// kernel_launch
// ---------------------------------------------------------------------------
extern "C" void kernel_launch(void* const* d_in, const int* in_sizes, int n_in,
                              void* d_out, int out_size)
{
    const float* inputs = (const float*)d_in[0];
    const float* prob   = (const float*)d_in[1];
    const float* Wioux  = (const float*)d_in[2];
    const float* bioux  = (const float*)d_in[3];
    const float* Wiouh  = (const float*)d_in[4];
    const float* biouh  = (const float*)d_in[5];
    const float* Wfx    = (const float*)d_in[6];
    const float* bfx    = (const float*)d_in[7];
    const float* Wfh    = (const float*)d_in[8];
    const float* bfh    = (const float*)d_in[9];
    float* out = (float*)d_out;

    u16 *pxhi,*pxlo,*phhi,*phlo,*pshi,*pslo;
    u16 *pWxh,*pWxl,*pWhh,*pWhl,*pWfxh,*pWfxl,*pWfhh,*pWfhl;
    float *phf,*pfx,*piou;
    cudaGetSymbolAddress((void**)&pxhi,  g_xhi);
    cudaGetSymbolAddress((void**)&pxlo,  g_xlo);
    cudaGetSymbolAddress((void**)&phhi,  g_hhi);
    cudaGetSymbolAddress((void**)&phlo,  g_hlo);
    cudaGetSymbolAddress((void**)&pshi,  g_shi);
    cudaGetSymbolAddress((void**)&pslo,  g_slo);
    cudaGetSymbolAddress((void**)&pWxh,  g_Wxh);
    cudaGetSymbolAddress((void**)&pWxl,  g_Wxl);
    cudaGetSymbolAddress((void**)&pWhh,  g_Whh);
    cudaGetSymbolAddress((void**)&pWhl,  g_Whl);
    cudaGetSymbolAddress((void**)&pWfxh, g_Wfxh);
    cudaGetSymbolAddress((void**)&pWfxl, g_Wfxl);
    cudaGetSymbolAddress((void**)&pWfhh, g_Wfhh);
    cudaGetSymbolAddress((void**)&pWfhl, g_Wfhl);
    cudaGetSymbolAddress((void**)&phf,   g_hf);
    cudaGetSymbolAddress((void**)&pfx,   g_fx);
    cudaGetSymbolAddress((void**)&piou,  g_iou);

    cudaFuncSetAttribute(gemm_plain, cudaFuncAttributeMaxDynamicSharedMemorySize, SMEM_PLAIN);
    cudaFuncSetAttribute(gemm_leaf,  cudaFuncAttributeMaxDynamicSharedMemorySize, SMEM_LEAF);

    // Split inputs + weights into bf16 hi/lo
    {
        size_t n4 = (size_t)N_NODES*NS/4;
        split_kernel<<<(unsigned)((n4+255)/256),256>>>(inputs, pxhi, pxlo, n4);
        split_kernel<<<(768*256/4+255)/256,256>>>(Wioux, pWxh,  pWxl,  768*256/4);
        split_kernel<<<(768*256/4+255)/256,256>>>(Wiouh, pWhh,  pWhl,  768*256/4);
        split_kernel<<<(256*256/4+255)/256,256>>>(Wfx,   pWfxh, pWfxl, 256*256/4);
        split_kernel<<<(256*256/4+255)/256,256>>>(Wfh,   pWfhh, pWfhl, 256*256/4);
    }

    // Leaf level: fused iou GEMM + activation (M = 262144 rows)
    gemm_leaf<<<dim3(4,2048),256,SMEM_LEAF>>>(
        pxhi + (size_t)LEAF_START*NS, pxlo + (size_t)LEAF_START*NS,
        pWxh, pWxl, bioux, biouh, 4096*BDIM, LEAF_START*BDIM);

    const int starts[5] = {0, 1, 9, 73, 585};
    const int counts[5] = {1, 8, 64, 512, 4096};

    for (int d=3; d>=0; d--){
        int s = starts[d], cnt = counts[d], cs = starts[d+1];
        int Mh = cnt*8*BDIM, Mp = cnt*BDIM;

        // hf = h[children] @ Wfh^T
        gemm_plain<<<dim3(4,(Mh+127)/128),256,SMEM_PLAIN>>>(
            phhi + (size_t)cs*NS, phlo + (size_t)cs*NS,
            nullptr, nullptr, pWfhh, pWfhl, nullptr, nullptr,
            nullptr, nullptr, phf, Mh, 256);

        // fx = x[parents] @ Wfx^T + bfx
        gemm_plain<<<dim3(4,(Mp+127)/128),256,SMEM_PLAIN>>>(
            pxhi + (size_t)s*NS, pxlo + (size_t)s*NS,
            nullptr, nullptr, pWfxh, pWfxl, nullptr, nullptr,
            bfx, nullptr, pfx, Mp, 256);

        // hsum (+ bf16 split)
        hsum_kernel<<<(cnt*NS+255)/256,256>>>(prob, s, cnt);

        // iou = x@Wioux^T + hsum@Wiouh^T + bioux + biouh
        gemm_plain<<<dim3(12,(Mp+127)/128),256,SMEM_PLAIN>>>(
            pxhi + (size_t)s*NS, pxlo + (size_t)s*NS, pshi, pslo,
            pWxh, pWxl, pWhh, pWhl,
            bioux, biouh, piou, Mp, 768);

        // gates + activation
        final_kernel<<<(cnt*NS+255)/256,256>>>(prob, bfh, s, cnt);
    }

    copy_out_kernel<<<(2*NS+255)/256,256>>>(out);
}

// round 4
// speedup vs baseline: 1.8847x; 1.0161x over previous
#include <cuda_runtime.h>
#include <cuda_bf16.h>
#include <math.h>
#include <stdint.h>

#define N_NODES 4681
#define BDIM    64
#define NS      16384
#define LEAF_START 585

typedef unsigned short u16;
typedef unsigned int   u32;
typedef unsigned long long u64;

// ---------------------------------------------------------------------------
// Static device scratch
// ---------------------------------------------------------------------------
__device__ __align__(256) float g_c  [(size_t)N_NODES*NS];
__device__ __align__(256) u16   g_hhi[(size_t)N_NODES*NS];
__device__ __align__(256) u16   g_hlo[(size_t)N_NODES*NS];
__device__ __align__(256) u16   g_xhi[(size_t)N_NODES*NS];
__device__ __align__(256) u16   g_xlo[(size_t)N_NODES*NS];
__device__ __align__(256) float g_hf [(size_t)4096*NS];
__device__ __align__(256) float g_fx [(size_t)512*NS];
__device__ __align__(256) u16   g_shi[(size_t)512*NS];
__device__ __align__(256) u16   g_slo[(size_t)512*NS];
__device__ __align__(256) float g_iou[(size_t)512*BDIM*768];
__device__ __align__(256) u16 g_Wxh[768*256],  g_Wxl[768*256];
__device__ __align__(256) u16 g_Whh[768*256],  g_Whl[768*256];
__device__ __align__(256) u16 g_Wfxh[256*256], g_Wfxl[256*256];
__device__ __align__(256) u16 g_Wfhh[256*256], g_Wfhl[256*256];

// ---------------------------------------------------------------------------
// Helpers
// ---------------------------------------------------------------------------
__device__ __forceinline__ float sig_fast(float x){ return 1.f/(1.f+__expf(-x)); }
__device__ __forceinline__ float tanh_fast(float x){ return 1.f - 2.f/(__expf(2.f*x)+1.f); }
__device__ __forceinline__ u16 f2bf(float x){ __nv_bfloat16 b = __float2bfloat16(x); return *(u16*)&b; }
__device__ __forceinline__ float bf2f(u16 v){ __nv_bfloat16 b = *(__nv_bfloat16*)&v; return __bfloat162float(b); }

__device__ __forceinline__ u32 smem_u32(const void* p){
    u32 a; asm("{ .reg .u64 t; cvta.to.shared.u64 t, %1; cvt.u32.u64 %0, t; }" : "=r"(a) : "l"(p)); return a;
}
__device__ __forceinline__ void cp16(u32 d, const void* s){
    asm volatile("cp.async.cg.shared.global [%0], [%1], 16;" :: "r"(d), "l"(s));
}
__device__ __forceinline__ void cp_commit(){ asm volatile("cp.async.commit_group;" ::: "memory"); }
__device__ __forceinline__ void cp_wait0(){ asm volatile("cp.async.wait_group 0;" ::: "memory"); }
__device__ __forceinline__ void cp_wait1(){ asm volatile("cp.async.wait_group 1;" ::: "memory"); }

__device__ __forceinline__ void ldsm4(u32 &r0,u32 &r1,u32 &r2,u32 &r3, u32 addr){
    asm volatile("ldmatrix.sync.aligned.m8n8.x4.shared.b16 {%0,%1,%2,%3}, [%4];"
        : "=r"(r0),"=r"(r1),"=r"(r2),"=r"(r3) : "r"(addr));
}
__device__ __forceinline__ void mma16816(float* c, const u32* a, const u32* b){
    asm volatile("mma.sync.aligned.m16n8k16.row.col.f32.bf16.bf16.f32 "
        "{%0,%1,%2,%3}, {%4,%5,%6,%7}, {%8,%9}, {%0,%1,%2,%3};"
        : "+f"(c[0]),"+f"(c[1]),"+f"(c[2]),"+f"(c[3])
        : "r"(a[0]),"r"(a[1]),"r"(a[2]),"r"(a[3]), "r"(b[0]),"r"(b[1]));
}

#define SWZ(o) ((u32)(o) ^ (((u32)(o)>>3)&0x70u))

// plain smem: A [0,32K), B [32K,64K), bias at 65536 (128 floats)
#define SMEM_PLAIN (65536 + 512)
// leaf smem:  A [0,32K), B [32K,80K), bias at 81920 (192 floats)
#define SMEM_LEAF  (81920 + 768)

// ---------------------------------------------------------------------------
// fp32 -> bf16 hi/lo split
// ---------------------------------------------------------------------------
__global__ void split_kernel(const float* __restrict__ src,
                             u16* __restrict__ hi, u16* __restrict__ lo, size_t n4)
{
    size_t i = (size_t)blockIdx.x*blockDim.x + threadIdx.x;
    if (i >= n4) return;
    float4 v = ((const float4*)src)[i];
    u16 h[4], l[4];
#pragma unroll
    for (int j=0;j<4;j++){
        float x = (&v.x)[j];
        u16 hb = f2bf(x);
        h[j] = hb; l[j] = f2bf(x - bf2f(hb));
    }
    ((ushort4*)hi)[i] = make_ushort4(h[0],h[1],h[2],h[3]);
    ((ushort4*)lo)[i] = make_ushort4(l[0],l[1],l[2],l[3]);
}

// ---------------------------------------------------------------------------
// Chunk loaders (cp.async, swizzled). 128 rows x 64 k-cols (128B) per chunk.
// ---------------------------------------------------------------------------
__device__ __forceinline__ void load_A_chunk(u32 aB, const u16* __restrict__ Ah,
    int rowBase, int kc, int M, int t)
{
#pragma unroll
    for (int i=0;i<4;i++){
        int e = t + i*256; int r = e>>3, s = e&7;
        int gr = rowBase + r; if (gr >= M) gr = M-1;
        cp16(aB + SWZ(r*128 + s*16), Ah + (size_t)gr*256 + kc + s*8);
    }
}
__device__ __forceinline__ void load_B_chunk128(u32 bB, const u16* __restrict__ Wh,
    int n0, int kc, int t)
{
#pragma unroll
    for (int i=0;i<4;i++){
        int e = t + i*256; int n = e>>3, s = e&7;
        cp16(bB + SWZ(n*128 + s*16), Wh + (size_t)(n0+n)*256 + kc + s*8);
    }
}

// ---------------------------------------------------------------------------
// gemm_plain: C[M, Nout] = A1@W1^T (+ A2@W2^T) (+ b1) (+ b2)
//   BM=128, BN=128; 8 warps (4m x 2n), warp tile 32x64.
//   3-pass bf16 hi/lo split per source.
// ---------------------------------------------------------------------------
__global__ void __launch_bounds__(256) gemm_plain(
    const u16* __restrict__ A1h, const u16* __restrict__ A1l,
    const u16* __restrict__ A2h, const u16* __restrict__ A2l,
    const u16* __restrict__ W1h, const u16* __restrict__ W1l,
    const u16* __restrict__ W2h, const u16* __restrict__ W2l,
    const float* __restrict__ b1, const float* __restrict__ b2,
    float* __restrict__ Cout, int M, int ldc)
{
    extern __shared__ __align__(1024) char smem[];
    const u32 sb = smem_u32(smem);
    const int t = threadIdx.x;
    const int n0 = blockIdx.x*128;
    const int rowBase = blockIdx.y*128;
    float* biasS = (float*)(smem + 65536);

    for (int i=t;i<128;i+=256){
        float v = 0.f;
        if (b1) v += b1[n0+i];
        if (b2) v += b2[n0+i];
        biasS[i] = v;
    }

    float C[2][8][4];
#pragma unroll
    for (int a=0;a<2;a++)
#pragma unroll
    for (int b=0;b<8;b++)
#pragma unroll
    for (int cc=0;cc<4;cc++) C[a][b][cc]=0.f;

    const int nc = (A2h != nullptr) ? 24 : 12;

    // chunk c: src=c/12, q=c%12, pass=q/4 (0:hh 1:hl 2:lh), kc=(q&3)*64
#define SEL_A(c) ((((c)%12)/4)==2 ? (((c)/12)? A2l:A1l) : (((c)/12)? A2h:A1h))
#define SEL_W(c) ((((c)%12)/4)==1 ? (((c)/12)? W2l:W1l) : (((c)/12)? W2h:W1h))
#define KC(c)    ((((c)%12)&3)*64)

    load_A_chunk(sb, SEL_A(0), rowBase, KC(0), M, t);
    load_B_chunk128(sb + 32768u, SEL_W(0), n0, KC(0), t);
    cp_commit();

    const int lane=t&31, wid=t>>5;
    const int wm=(wid&3)*32, wn=(wid>>2)*64;
    const u32 aRow  = (u32)(wm + (lane&15));
    const u32 aCol0 = (u32)((lane>>4)*16);
    const u32 bRow  = (u32)(wn + (lane&7) + ((lane>>4)&1)*8);
    const u32 bCol0 = (u32)(((lane>>3)&1)*16);

    for (int c=0;c<nc;c++){
        if (c+1<nc){
            int nb=(c+1)&1;
            load_A_chunk(sb + nb*16384u, SEL_A(c+1), rowBase, KC(c+1), M, t);
            load_B_chunk128(sb + 32768u + nb*16384u, SEL_W(c+1), n0, KC(c+1), t);
            cp_commit();
            cp_wait1();
        } else cp_wait0();
        __syncthreads();

        const u32 aB = sb + (u32)(c&1)*16384u;
        const u32 bB = sb + 32768u + (u32)(c&1)*16384u;
#pragma unroll
        for (int ks=0;ks<4;ks++){
            u32 a0[4], a1[4];
            ldsm4(a0[0],a0[1],a0[2],a0[3], aB + SWZ(aRow*128      + ks*32 + aCol0));
            ldsm4(a1[0],a1[1],a1[2],a1[3], aB + SWZ((aRow+16)*128 + ks*32 + aCol0));
#pragma unroll
            for (int nb=0;nb<4;nb++){
                u32 bf[4];
                ldsm4(bf[0],bf[1],bf[2],bf[3], bB + SWZ((bRow+nb*16)*128 + ks*32 + bCol0));
                mma16816(C[0][2*nb+0], a0, bf+0); mma16816(C[0][2*nb+1], a0, bf+2);
                mma16816(C[1][2*nb+0], a1, bf+0); mma16816(C[1][2*nb+1], a1, bf+2);
            }
        }
        if (c+1<nc) __syncthreads();
    }
#undef SEL_A
#undef SEL_W
#undef KC

    // epilogue
#pragma unroll
    for (int mt=0;mt<2;mt++){
        int r0 = rowBase + wm + mt*16 + (lane>>2);
#pragma unroll
        for (int nt=0;nt<8;nt++){
            int cl = wn + nt*8 + (lane&3)*2;
            float bz0 = biasS[cl], bz1 = biasS[cl+1];
            if (r0 < M)
                *(float2*)(Cout + (size_t)r0*ldc + n0 + cl) =
                    make_float2(C[mt][nt][0]+bz0, C[mt][nt][1]+bz1);
            if (r0+8 < M)
                *(float2*)(Cout + (size_t)(r0+8)*ldc + n0 + cl) =
                    make_float2(C[mt][nt][2]+bz0, C[mt][nt][3]+bz1);
        }
    }
}

// ---------------------------------------------------------------------------
// gemm_leaf: fused iou GEMM + LSTM activation for leaves (unchanged from R3).
// ---------------------------------------------------------------------------
__global__ void __launch_bounds__(256) gemm_leaf(
    const u16* __restrict__ Ah_, const u16* __restrict__ Al_,
    const u16* __restrict__ Wh_, const u16* __restrict__ Wl_,
    const float* __restrict__ bx, const float* __restrict__ bh,
    int M, int outRowBase)
{
    extern __shared__ __align__(1024) char smem[];
    const u32 sb = smem_u32(smem);
    const int t = threadIdx.x;
    const int m0 = blockIdx.x*64;
    const int rowBase = blockIdx.y*128;
    float* biasS = (float*)(smem + 81920);

    for (int i=t;i<192;i+=256){
        int g=i>>6, cc=i&63;
        biasS[i] = bx[g*256+m0+cc] + bh[g*256+m0+cc];
    }

    float Cg[3][2][4][4];
#pragma unroll
    for (int g=0;g<3;g++)
#pragma unroll
    for (int a=0;a<2;a++)
#pragma unroll
    for (int b=0;b<4;b++)
#pragma unroll
    for (int cc=0;cc<4;cc++) Cg[g][a][b][cc]=0.f;

#define LSEL_A(c) (((c)/4)==2 ? Al_ : Ah_)
#define LSEL_W(c) (((c)/4)==1 ? Wl_ : Wh_)
#define LKC(c)    (((c)&3)*64)

#define LOAD_LEAF_B(bB, Wp, kc) \
    { _Pragma("unroll") \
      for (int i=0;i<6;i++){ \
        int e = t + i*256; int g = e>>9, f = e&511, n = f>>3, s = f&7; \
        cp16((bB) + (u32)g*8192u + SWZ(n*128 + s*16), \
             (Wp) + (size_t)(g*256 + m0 + n)*256 + (kc) + s*8); } }

    load_A_chunk(sb, LSEL_A(0), rowBase, LKC(0), M, t);
    LOAD_LEAF_B(sb + 32768u, LSEL_W(0), LKC(0));
    cp_commit();

    const int lane=t&31, wid=t>>5;
    const int wm=(wid&3)*32, wn=(wid>>2)*32;
    const u32 aRow  = (u32)(wm + (lane&15));
    const u32 aCol0 = (u32)((lane>>4)*16);
    const u32 bRow  = (u32)(wn + (lane&7) + ((lane>>4)&1)*8);
    const u32 bCol0 = (u32)(((lane>>3)&1)*16);

    for (int c=0;c<12;c++){
        if (c+1<12){
            int nb=(c+1)&1;
            load_A_chunk(sb + nb*16384u, LSEL_A(c+1), rowBase, LKC(c+1), M, t);
            LOAD_LEAF_B(sb + 32768u + (u32)nb*24576u, LSEL_W(c+1), LKC(c+1));
            cp_commit();
            cp_wait1();
        } else cp_wait0();
        __syncthreads();

        const u32 aB = sb + (u32)(c&1)*16384u;
        const u32 bB = sb + 32768u + (u32)(c&1)*24576u;
#pragma unroll
        for (int ks=0;ks<4;ks++){
            u32 a0[4], a1[4];
            ldsm4(a0[0],a0[1],a0[2],a0[3], aB + SWZ(aRow*128      + ks*32 + aCol0));
            ldsm4(a1[0],a1[1],a1[2],a1[3], aB + SWZ((aRow+16)*128 + ks*32 + aCol0));
#pragma unroll
            for (int g=0;g<3;g++){
                u32 b0[4], b1f[4];
                u32 gB = bB + (u32)g*8192u;
                ldsm4(b0[0],b0[1],b0[2],b0[3],   gB + SWZ(bRow*128      + ks*32 + bCol0));
                ldsm4(b1f[0],b1f[1],b1f[2],b1f[3], gB + SWZ((bRow+16)*128 + ks*32 + bCol0));
                mma16816(Cg[g][0][0], a0, b0+0); mma16816(Cg[g][0][1], a0, b0+2);
                mma16816(Cg[g][0][2], a0, b1f+0); mma16816(Cg[g][0][3], a0, b1f+2);
                mma16816(Cg[g][1][0], a1, b0+0); mma16816(Cg[g][1][1], a1, b0+2);
                mma16816(Cg[g][1][2], a1, b1f+0); mma16816(Cg[g][1][3], a1, b1f+2);
            }
        }
        if (c+1<12) __syncthreads();
    }
#undef LSEL_A
#undef LSEL_W
#undef LKC
#undef LOAD_LEAF_B

#pragma unroll
    for (int mt=0;mt<2;mt++){
        int rb = wm + mt*16 + (lane>>2);
#pragma unroll
        for (int h2=0;h2<2;h2++){
            int row = rowBase + rb + h2*8;
#pragma unroll
            for (int nt=0;nt<4;nt++){
                int cl = wn + nt*8 + (lane&3)*2;
                float cs2[2]; u16 hh2[2], hl2[2];
#pragma unroll
                for (int e=0;e<2;e++){
                    float iv = Cg[0][mt][nt][h2*2+e] + biasS[cl+e];
                    float ov = Cg[1][mt][nt][h2*2+e] + biasS[64+cl+e];
                    float uv = Cg[2][mt][nt][h2*2+e] + biasS[128+cl+e];
                    float c_ = sig_fast(iv)*tanh_fast(uv);
                    float h_ = sig_fast(ov)*tanh_fast(c_);
                    cs2[e]=c_;
                    u16 hb=f2bf(h_); hh2[e]=hb; hl2[e]=f2bf(h_-bf2f(hb));
                }
                size_t idx = ((size_t)(outRowBase+row))*256 + m0 + cl;
                *(float2*)(g_c+idx) = make_float2(cs2[0],cs2[1]);
                *(u32*)(g_hhi+idx)  = (u32)hh2[0] | ((u32)hh2[1]<<16);
                *(u32*)(g_hlo+idx)  = (u32)hl2[0] | ((u32)hl2[1]<<16);
            }
        }
    }
}

// ---------------------------------------------------------------------------
// hsum
// ---------------------------------------------------------------------------
__global__ void hsum_kernel(const float* __restrict__ prob, int s, int cnt)
{
    int idx = blockIdx.x*blockDim.x + threadIdx.x;
    if (idx >= cnt*NS) return;
    int p = idx >> 14, r = idx & (NS-1);
    int pg = s + p, cg = 8*pg + 1;
    const float* pr = prob + (size_t)pg*N_NODES + cg;
    float acc = 0.f;
#pragma unroll
    for (int j=0;j<8;j++){
        size_t o = (size_t)(cg+j)*NS + r;
        acc += pr[j] * (bf2f(g_hhi[o]) + bf2f(g_hlo[o]));
    }
    u16 hb = f2bf(acc);
    g_shi[idx] = hb;
    g_slo[idx] = f2bf(acc - bf2f(hb));
}

// ---------------------------------------------------------------------------
// final: forget gates + cell/hidden activation
// ---------------------------------------------------------------------------
__global__ void final_kernel(const float* __restrict__ prob,
                             const float* __restrict__ bfh, int s, int cnt)
{
    int idx = blockIdx.x*blockDim.x + threadIdx.x;
    if (idx >= cnt*NS) return;
    int p = idx >> 14, r = idx & (NS-1);
    int m = idx & 255;
    int row = idx >> 8;
    int pg = s + p, cg = 8*pg + 1;

    const float* iou = g_iou + (size_t)row*768 + m;
    float iv = iou[0], ov = iou[256], uv = iou[512];
    float fxv = g_fx[idx];
    float bf = bfh[m];

    const float* pr = prob + (size_t)pg*N_NODES + cg;
    float acc = 0.f;
#pragma unroll
    for (int j=0;j<8;j++){
        float pw  = pr[j];
        float hf  = g_hf[(size_t)(8*p+j)*NS + r];
        float cch = g_c[(size_t)(cg+j)*NS + r];
        float f = sig_fast(pw*hf + bf + fxv);
        acc += f * pw * cch;
    }
    float cc = sig_fast(iv)*tanh_fast(uv) + acc;
    float hh = sig_fast(ov)*tanh_fast(cc);
    g_c[(size_t)pg*NS + r] = cc;
    u16 hb = f2bf(hh);
    g_hhi[(size_t)pg*NS + r] = hb;
    g_hlo[(size_t)pg*NS + r] = f2bf(hh - bf2f(hb));
}

__global__ void copy_out_kernel(float* __restrict__ out)
{
    int i = blockIdx.x*blockDim.x + threadIdx.x;
    if (i < NS)          out[i] = g_c[i];
    else if (i < 2*NS)   out[i] = bf2f(g_hhi[i-NS]) + bf2f(g_hlo[i-NS]);
}

// ---------------------------------------------------------------------------
// kernel_launch
// ---------------------------------------------------------------------------
extern "C" void kernel_launch(void* const* d_in, const int* in_sizes, int n_in,
                              void* d_out, int out_size)
{
    const float* inputs = (const float*)d_in[0];
    const float* prob   = (const float*)d_in[1];
    const float* Wioux  = (const float*)d_in[2];
    const float* bioux  = (const float*)d_in[3];
    const float* Wiouh  = (const float*)d_in[4];
    const float* biouh  = (const float*)d_in[5];
    const float* Wfx    = (const float*)d_in[6];
    const float* bfx    = (const float*)d_in[7];
    const float* Wfh    = (const float*)d_in[8];
    const float* bfh    = (const float*)d_in[9];
    float* out = (float*)d_out;

    u16 *pxhi,*pxlo,*phhi,*phlo,*pshi,*pslo;
    u16 *pWxh,*pWxl,*pWhh,*pWhl,*pWfxh,*pWfxl,*pWfhh,*pWfhl;
    float *phf,*pfx,*piou;
    cudaGetSymbolAddress((void**)&pxhi,  g_xhi);
    cudaGetSymbolAddress((void**)&pxlo,  g_xlo);
    cudaGetSymbolAddress((void**)&phhi,  g_hhi);
    cudaGetSymbolAddress((void**)&phlo,  g_hlo);
    cudaGetSymbolAddress((void**)&pshi,  g_shi);
    cudaGetSymbolAddress((void**)&pslo,  g_slo);
    cudaGetSymbolAddress((void**)&pWxh,  g_Wxh);
    cudaGetSymbolAddress((void**)&pWxl,  g_Wxl);
    cudaGetSymbolAddress((void**)&pWhh,  g_Whh);
    cudaGetSymbolAddress((void**)&pWhl,  g_Whl);
    cudaGetSymbolAddress((void**)&pWfxh, g_Wfxh);
    cudaGetSymbolAddress((void**)&pWfxl, g_Wfxl);
    cudaGetSymbolAddress((void**)&pWfhh, g_Wfhh);
    cudaGetSymbolAddress((void**)&pWfhl, g_Wfhl);
    cudaGetSymbolAddress((void**)&phf,   g_hf);
    cudaGetSymbolAddress((void**)&pfx,   g_fx);
    cudaGetSymbolAddress((void**)&piou,  g_iou);

    cudaFuncSetAttribute(gemm_plain, cudaFuncAttributeMaxDynamicSharedMemorySize, SMEM_PLAIN);
    cudaFuncSetAttribute(gemm_leaf,  cudaFuncAttributeMaxDynamicSharedMemorySize, SMEM_LEAF);

    // Split inputs + weights into bf16 hi/lo
    {
        size_t n4 = (size_t)N_NODES*NS/4;
        split_kernel<<<(unsigned)((n4+255)/256),256>>>(inputs, pxhi, pxlo, n4);
        split_kernel<<<(768*256/4+255)/256,256>>>(Wioux, pWxh,  pWxl,  768*256/4);
        split_kernel<<<(768*256/4+255)/256,256>>>(Wiouh, pWhh,  pWhl,  768*256/4);
        split_kernel<<<(256*256/4+255)/256,256>>>(Wfx,   pWfxh, pWfxl, 256*256/4);
        split_kernel<<<(256*256/4+255)/256,256>>>(Wfh,   pWfhh, pWfhl, 256*256/4);
    }

    // Leaf level: fused iou GEMM + activation (M = 262144 rows)
    gemm_leaf<<<dim3(4,2048),256,SMEM_LEAF>>>(
        pxhi + (size_t)LEAF_START*NS, pxlo + (size_t)LEAF_START*NS,
        pWxh, pWxl, bioux, biouh, 4096*BDIM, LEAF_START*BDIM);

    const int starts[5] = {0, 1, 9, 73, 585};
    const int counts[5] = {1, 8, 64, 512, 4096};

    for (int d=3; d>=0; d--){
        int s = starts[d], cnt = counts[d], cs = starts[d+1];
        int Mh = cnt*8*BDIM, Mp = cnt*BDIM;

        // hf = h[children] @ Wfh^T
        gemm_plain<<<dim3(2,(Mh+127)/128),256,SMEM_PLAIN>>>(
            phhi + (size_t)cs*NS, phlo + (size_t)cs*NS,
            nullptr, nullptr, pWfhh, pWfhl, nullptr, nullptr,
            nullptr, nullptr, phf, Mh, 256);

        // fx = x[parents] @ Wfx^T + bfx
        gemm_plain<<<dim3(2,(Mp+127)/128),256,SMEM_PLAIN>>>(
            pxhi + (size_t)s*NS, pxlo + (size_t)s*NS,
            nullptr, nullptr, pWfxh, pWfxl, nullptr, nullptr,
            bfx, nullptr, pfx, Mp, 256);

        // hsum (+ bf16 split)
        hsum_kernel<<<(cnt*NS+255)/256,256>>>(prob, s, cnt);

        // iou = x@Wioux^T + hsum@Wiouh^T + bioux + biouh
        gemm_plain<<<dim3(6,(Mp+127)/128),256,SMEM_PLAIN>>>(
            pxhi + (size_t)s*NS, pxlo + (size_t)s*NS, pshi, pslo,
            pWxh, pWxl, pWhh, pWhl,
            bioux, biouh, piou, Mp, 768);

        // gates + activation
        final_kernel<<<(cnt*NS+255)/256,256>>>(prob, bfh, s, cnt);
    }

    copy_out_kernel<<<(2*NS+255)/256,256>>>(out);
}